// round 2
// baseline (speedup 1.0000x reference)
#include <cuda_runtime.h>

#define NMAX   100000
#define EMAX   1600000
#define DIN    64
#define NHEAD  4
#define HDIM   16
#define FEAT   64   // NHEAD*HDIM

// -------- scratch (static device globals; no allocations allowed) ----------
__device__ __align__(16) static float g_h[(size_t)NMAX * FEAT];   // projected node features
__device__ static float g_u[NMAX];
__device__ static float g_v[NMAX];
__device__ __align__(16) static float g_as[NMAX * NHEAD];
__device__ __align__(16) static float g_ad[NMAX * NHEAD];

__device__ static int g_deg[NMAX];
__device__ static int g_cursor[NMAX];
__device__ static int g_offs[NMAX + 1];
__device__ static int g_srcs[EMAX];     // src node id per edge, sorted by dst

struct Params {
    float cu[DIN];   // Wd @ (Wf[0:64]  + Wf[128:192])
    float cv[DIN];   // Wd @ (Wf[64:128] - Wf[128:192])
    float off;       // bd . (wfu + wfv) + bf
    float ba;        // attention bias scalar
};
__device__ static Params g_P;

// ---------------------------------------------------------------------------
// 1) Fold the rank-1 edge linears into per-node projection vectors.
// ---------------------------------------------------------------------------
__global__ void precompute_kernel(const float* __restrict__ Wd,
                                  const float* __restrict__ bd,
                                  const float* __restrict__ Wf,
                                  const float* __restrict__ bf,
                                  const float* __restrict__ ba) {
    __shared__ float wfu[DIN], wfv[DIN], red[DIN];
    int t = threadIdx.x;   // 64 threads
    float f0 = Wf[t], f1 = Wf[DIN + t], f2 = Wf[2 * DIN + t];
    wfu[t] = f0 + f2;
    wfv[t] = f1 - f2;
    __syncthreads();
    float cu = 0.f, cv = 0.f;
#pragma unroll 8
    for (int j = 0; j < DIN; j++) {
        float w = Wd[t * DIN + j];
        cu += w * wfu[j];
        cv += w * wfv[j];
    }
    g_P.cu[t] = cu;
    g_P.cv[t] = cv;
    red[t] = bd[t] * (wfu[t] + wfv[t]);
    __syncthreads();
    if (t == 0) {
        float s = bf[0];
        for (int j = 0; j < DIN; j++) s += red[j];
        g_P.off = s;
        g_P.ba  = ba[0];
    }
}

// ---------------------------------------------------------------------------
// 2) Zero degree + cursor arrays.
// ---------------------------------------------------------------------------
__global__ void zero_dc_kernel(int N) {
    int i = blockIdx.x * blockDim.x + threadIdx.x;
    int stride = gridDim.x * blockDim.x;
    for (int k = i; k < N; k += stride) { g_deg[k] = 0; g_cursor[k] = 0; }
}

// ---------------------------------------------------------------------------
// 3) Degree histogram over dst.
// ---------------------------------------------------------------------------
__global__ void hist_kernel(const int* __restrict__ dst, int E) {
    int e = blockIdx.x * blockDim.x + threadIdx.x;
    if (e < E) atomicAdd(&g_deg[dst[e]], 1);
}

// ---------------------------------------------------------------------------
// 4) One-block exclusive scan of g_deg -> g_offs (N is only 100k).
// ---------------------------------------------------------------------------
__global__ void scan_kernel(int N) {
    __shared__ int sums[1024];
    int t = threadIdx.x;
    int CH = (N + 1023) / 1024;
    int beg = t * CH;
    int s = 0;
    for (int i = 0; i < CH; i++) {
        int idx = beg + i;
        if (idx < N) s += g_deg[idx];
    }
    sums[t] = s;
    __syncthreads();
    // Hillis-Steele inclusive scan over 1024 partials
    for (int o = 1; o < 1024; o <<= 1) {
        int tmp = (t >= o) ? sums[t - o] : 0;
        __syncthreads();
        sums[t] += tmp;
        __syncthreads();
    }
    int run = sums[t] - s;   // exclusive base for this chunk
    for (int i = 0; i < CH; i++) {
        int idx = beg + i;
        if (idx < N) {
            g_offs[idx] = run;
            run += g_deg[idx];
        }
    }
    if (t == 1023) g_offs[N] = sums[1023];
}

// ---------------------------------------------------------------------------
// 5) Scatter src ids into dst-sorted order.
// ---------------------------------------------------------------------------
__global__ void scatter_kernel(const int* __restrict__ src,
                               const int* __restrict__ dst, int E) {
    int e = blockIdx.x * blockDim.x + threadIdx.x;
    if (e >= E) return;
    int d = dst[e];
    int pos = g_offs[d] + atomicAdd(&g_cursor[d], 1);
    g_srcs[pos] = src[e];
}

// ---------------------------------------------------------------------------
// 6) Per-node projections: h = x@Wl + bl, u = x.cu, v = x.cv,
//    a_s/a_d = per-head dot with Wa halves.
// ---------------------------------------------------------------------------
__global__ void __launch_bounds__(128)
node_kernel(const float* __restrict__ x,
            const float* __restrict__ Wl,
            const float* __restrict__ bl,
            const float* __restrict__ Wa,
            int N) {
    __shared__ float s_wl[DIN * FEAT];
    __shared__ float s_bl[FEAT];
    __shared__ float s_wa[2 * HDIM];
    __shared__ float s_cu[DIN], s_cv[DIN];

    for (int i = threadIdx.x; i < DIN * FEAT; i += blockDim.x) s_wl[i] = Wl[i];
    if (threadIdx.x < FEAT) {
        s_bl[threadIdx.x] = bl[threadIdx.x];
        s_cu[threadIdx.x] = g_P.cu[threadIdx.x];
        s_cv[threadIdx.x] = g_P.cv[threadIdx.x];
    }
    if (threadIdx.x < 2 * HDIM) s_wa[threadIdx.x] = Wa[threadIdx.x];
    __syncthreads();

    int n = blockIdx.x * blockDim.x + threadIdx.x;
    if (n >= N) return;

    float acc[FEAT];
#pragma unroll
    for (int o = 0; o < FEAT; o++) acc[o] = s_bl[o];
    float u = 0.f, v = 0.f;

    const float4* xr = reinterpret_cast<const float4*>(x + (size_t)n * DIN);
#pragma unroll 1
    for (int i4 = 0; i4 < DIN / 4; i4++) {
        float4 xv = xr[i4];
        float xs[4] = {xv.x, xv.y, xv.z, xv.w};
#pragma unroll
        for (int j = 0; j < 4; j++) {
            int i = i4 * 4 + j;
            float xi = xs[j];
            u += xi * s_cu[i];
            v += xi * s_cv[i];
            const float4* wrow = reinterpret_cast<const float4*>(&s_wl[i * FEAT]);
#pragma unroll
            for (int o4 = 0; o4 < FEAT / 4; o4++) {
                float4 wv = wrow[o4];
                acc[o4 * 4 + 0] += xi * wv.x;
                acc[o4 * 4 + 1] += xi * wv.y;
                acc[o4 * 4 + 2] += xi * wv.z;
                acc[o4 * 4 + 3] += xi * wv.w;
            }
        }
    }

    float4* hout = reinterpret_cast<float4*>(&g_h[(size_t)n * FEAT]);
#pragma unroll
    for (int o4 = 0; o4 < FEAT / 4; o4++)
        hout[o4] = make_float4(acc[o4 * 4 + 0], acc[o4 * 4 + 1],
                               acc[o4 * 4 + 2], acc[o4 * 4 + 3]);

    g_u[n] = u;
    g_v[n] = v;

#pragma unroll
    for (int h = 0; h < NHEAD; h++) {
        float as = 0.f, ad = 0.f;
#pragma unroll
        for (int k = 0; k < HDIM; k++) {
            float hv = acc[h * HDIM + k];
            as += hv * s_wa[k];
            ad += hv * s_wa[HDIM + k];
        }
        g_as[n * NHEAD + h] = as;
        g_ad[n * NHEAD + h] = ad;
    }
}

// ---------------------------------------------------------------------------
// 7) CSR reduce: 16 threads per dst node (t*4 = contiguous float4 of the 64
//    output features; head = t>>2). Register accumulation, no atomics,
//    normalization fused. Every output element written exactly once.
// ---------------------------------------------------------------------------
__global__ void __launch_bounds__(256)
reduce_kernel(float* __restrict__ out, int N) {
    int gid = blockIdx.x * blockDim.x + threadIdx.x;
    int n = gid >> 4;
    if (n >= N) return;
    int t = gid & 15;
    int head = t >> 2;

    int beg = g_offs[n];
    int end = g_offs[n + 1];

    float vofs = g_v[n] + g_P.off;     // folded per-node sign offset
    float adb  = g_ad[n * NHEAD + head] + g_P.ba;

    float4 acc = make_float4(0.f, 0.f, 0.f, 0.f);
    float dsum = 0.f;

#pragma unroll 2
    for (int p = beg; p < end; p++) {
        int s = __ldg(&g_srcs[p]);
        float arg = g_u[s] + vofs;
        float sg = (arg > 0.f) ? 1.f : ((arg < 0.f) ? -1.f : 0.f);
        float al = sg * g_as[s * NHEAD + head] + adb;
        al = (al > 0.f) ? al : 0.01f * al;          // leaky_relu
        float w = __expf(al);
        float4 hv = *reinterpret_cast<const float4*>(&g_h[(size_t)s * FEAT + t * 4]);
        float ws = w * sg;
        acc.x += ws * hv.x;
        acc.y += ws * hv.y;
        acc.z += ws * hv.z;
        acc.w += ws * hv.w;
        dsum += w;
    }

    float inv = 1.f / fmaxf(dsum, 1e-16f);
    *reinterpret_cast<float4*>(&out[(size_t)n * FEAT + t * 4]) =
        make_float4(acc.x * inv, acc.y * inv, acc.z * inv, acc.w * inv);
}

// ---------------------------------------------------------------------------
extern "C" void kernel_launch(void* const* d_in, const int* in_sizes, int n_in,
                              void* d_out, int out_size) {
    const float* x   = (const float*)d_in[0];
    const int*   src = (const int*)  d_in[1];
    const int*   dst = (const int*)  d_in[2];
    const float* Wl  = (const float*)d_in[3];
    const float* bl  = (const float*)d_in[4];
    const float* Wa  = (const float*)d_in[5];
    const float* ba  = (const float*)d_in[6];
    const float* Wd  = (const float*)d_in[7];
    const float* bd  = (const float*)d_in[8];
    const float* Wf  = (const float*)d_in[9];
    const float* bf  = (const float*)d_in[10];
    float* out = (float*)d_out;

    int N = in_sizes[0] / DIN;
    int E = in_sizes[1];

    precompute_kernel<<<1, 64>>>(Wd, bd, Wf, bf, ba);
    zero_dc_kernel<<<256, 256>>>(N);
    hist_kernel<<<(E + 255) / 256, 256>>>(dst, E);
    scan_kernel<<<1, 1024>>>(N);
    scatter_kernel<<<(E + 255) / 256, 256>>>(src, dst, E);
    node_kernel<<<(N + 127) / 128, 128>>>(x, Wl, bl, Wa, N);

    long long threads = (long long)N * 16;
    int blocks = (int)((threads + 255) / 256);
    reduce_kernel<<<blocks, 256>>>(out, N);
}

// round 3
// speedup vs baseline: 1.6126x; 1.6126x over previous
#include <cuda_runtime.h>

#define NMAX   100000
#define EMAX   1600000
#define DIN    64
#define NHEAD  4
#define HDIM   16
#define FEAT   64   // NHEAD*HDIM
#define SCAN_B 1024
#define NBMAX  256

// -------- scratch (static device globals; no allocations allowed) ----------
__device__ __align__(16) static float g_h[(size_t)NMAX * FEAT];   // projected node features
__device__ static float g_u[NMAX];
__device__ static float g_v[NMAX];
__device__ __align__(16) static float g_as[NMAX * NHEAD];
__device__ __align__(16) static float g_ad[NMAX * NHEAD];

__device__ static int g_deg[NMAX];
__device__ static int g_cursor[NMAX];      // initialized to offs; scatter bumps it
__device__ static int g_offs[NMAX + 1];
__device__ static int g_srcs[EMAX];        // src node id per edge, sorted by dst
__device__ static int g_bsum[NBMAX];
__device__ static int g_bbase[NBMAX];

struct Params {
    float cu[DIN];   // Wd @ (Wf[0:64]  + Wf[128:192])
    float cv[DIN];   // Wd @ (Wf[64:128] - Wf[128:192])
    float off;       // bd . (wfu + wfv) + bf
    float ba;        // attention bias scalar
};
__device__ static Params g_P;

// ---------------------------------------------------------------------------
// 1) Fold the rank-1 edge linears into per-node projection vectors.
// ---------------------------------------------------------------------------
__global__ void precompute_kernel(const float* __restrict__ Wd,
                                  const float* __restrict__ bd,
                                  const float* __restrict__ Wf,
                                  const float* __restrict__ bf,
                                  const float* __restrict__ ba) {
    __shared__ float wfu[DIN], wfv[DIN], red[DIN];
    int t = threadIdx.x;   // 64 threads
    float f0 = Wf[t], f1 = Wf[DIN + t], f2 = Wf[2 * DIN + t];
    wfu[t] = f0 + f2;
    wfv[t] = f1 - f2;
    __syncthreads();
    float cu = 0.f, cv = 0.f;
#pragma unroll 8
    for (int j = 0; j < DIN; j++) {
        float w = Wd[t * DIN + j];
        cu += w * wfu[j];
        cv += w * wfv[j];
    }
    g_P.cu[t] = cu;
    g_P.cv[t] = cv;
    red[t] = bd[t] * (wfu[t] + wfv[t]);
    __syncthreads();
    if (t == 0) {
        float s = bf[0];
        for (int j = 0; j < DIN; j++) s += red[j];
        g_P.off = s;
        g_P.ba  = ba[0];
    }
}

// ---------------------------------------------------------------------------
// 2) Zero degree array.
// ---------------------------------------------------------------------------
__global__ void zero_deg_kernel(int N) {
    int i = blockIdx.x * blockDim.x + threadIdx.x;
    if (i < N) g_deg[i] = 0;
}

// ---------------------------------------------------------------------------
// 3) Degree histogram over dst.
// ---------------------------------------------------------------------------
__global__ void hist_kernel(const int* __restrict__ dst, int E) {
    int e = blockIdx.x * blockDim.x + threadIdx.x;
    if (e < E) atomicAdd(&g_deg[dst[e]], 1);
}

// ---------------------------------------------------------------------------
// 4a) Per-block partial sums of g_deg.
// ---------------------------------------------------------------------------
__global__ void scan_partial_kernel(int N) {
    __shared__ int sm[SCAN_B];
    int idx = blockIdx.x * SCAN_B + threadIdx.x;
    sm[threadIdx.x] = (idx < N) ? g_deg[idx] : 0;
    __syncthreads();
#pragma unroll
    for (int o = SCAN_B / 2; o > 0; o >>= 1) {
        if (threadIdx.x < o) sm[threadIdx.x] += sm[threadIdx.x + o];
        __syncthreads();
    }
    if (threadIdx.x == 0) g_bsum[blockIdx.x] = sm[0];
}

// ---------------------------------------------------------------------------
// 4b) Exclusive scan of the (<=256) block sums; also write total at offs[N].
// ---------------------------------------------------------------------------
__global__ void scan_base_kernel(int NB, int N) {
    __shared__ int sm[NBMAX];
    int t = threadIdx.x;   // 256 threads
    int v = (t < NB) ? g_bsum[t] : 0;
    sm[t] = v;
    __syncthreads();
#pragma unroll
    for (int o = 1; o < NBMAX; o <<= 1) {
        int tmp = (t >= o) ? sm[t - o] : 0;
        __syncthreads();
        sm[t] += tmp;
        __syncthreads();
    }
    if (t < NB) g_bbase[t] = sm[t] - v;
    if (t == NBMAX - 1) g_offs[N] = sm[NBMAX - 1];
}

// ---------------------------------------------------------------------------
// 4c) Per-block exclusive scan + base; also seeds the scatter cursor.
// ---------------------------------------------------------------------------
__global__ void scan_final_kernel(int N) {
    __shared__ int sm[SCAN_B];
    int idx = blockIdx.x * SCAN_B + threadIdx.x;
    int v = (idx < N) ? g_deg[idx] : 0;
    sm[threadIdx.x] = v;
    __syncthreads();
#pragma unroll
    for (int o = 1; o < SCAN_B; o <<= 1) {
        int tmp = (threadIdx.x >= o) ? sm[threadIdx.x - o] : 0;
        __syncthreads();
        sm[threadIdx.x] += tmp;
        __syncthreads();
    }
    if (idx < N) {
        int off = g_bbase[blockIdx.x] + sm[threadIdx.x] - v;
        g_offs[idx] = off;
        g_cursor[idx] = off;
    }
}

// ---------------------------------------------------------------------------
// 5) Scatter src ids into dst-sorted order (cursor pre-seeded with offsets).
// ---------------------------------------------------------------------------
__global__ void scatter_kernel(const int* __restrict__ src,
                               const int* __restrict__ dst, int E) {
    int e = blockIdx.x * blockDim.x + threadIdx.x;
    if (e >= E) return;
    int pos = atomicAdd(&g_cursor[dst[e]], 1);
    g_srcs[pos] = src[e];
}

// ---------------------------------------------------------------------------
// 6) Per-node projections: h = x@Wl + bl, u = x.cu, v = x.cv,
//    a_s/a_d = per-head dot with Wa halves.
// ---------------------------------------------------------------------------
__global__ void __launch_bounds__(128)
node_kernel(const float* __restrict__ x,
            const float* __restrict__ Wl,
            const float* __restrict__ bl,
            const float* __restrict__ Wa,
            int N) {
    __shared__ float s_wl[DIN * FEAT];
    __shared__ float s_bl[FEAT];
    __shared__ float s_wa[2 * HDIM];
    __shared__ float s_cu[DIN], s_cv[DIN];

    for (int i = threadIdx.x; i < DIN * FEAT; i += blockDim.x) s_wl[i] = Wl[i];
    if (threadIdx.x < FEAT) {
        s_bl[threadIdx.x] = bl[threadIdx.x];
        s_cu[threadIdx.x] = g_P.cu[threadIdx.x];
        s_cv[threadIdx.x] = g_P.cv[threadIdx.x];
    }
    if (threadIdx.x < 2 * HDIM) s_wa[threadIdx.x] = Wa[threadIdx.x];
    __syncthreads();

    int n = blockIdx.x * blockDim.x + threadIdx.x;
    if (n >= N) return;

    float acc[FEAT];
#pragma unroll
    for (int o = 0; o < FEAT; o++) acc[o] = s_bl[o];
    float u = 0.f, v = 0.f;

    const float4* xr = reinterpret_cast<const float4*>(x + (size_t)n * DIN);
#pragma unroll 1
    for (int i4 = 0; i4 < DIN / 4; i4++) {
        float4 xv = xr[i4];
        float xs[4] = {xv.x, xv.y, xv.z, xv.w};
#pragma unroll
        for (int j = 0; j < 4; j++) {
            int i = i4 * 4 + j;
            float xi = xs[j];
            u += xi * s_cu[i];
            v += xi * s_cv[i];
            const float4* wrow = reinterpret_cast<const float4*>(&s_wl[i * FEAT]);
#pragma unroll
            for (int o4 = 0; o4 < FEAT / 4; o4++) {
                float4 wv = wrow[o4];
                acc[o4 * 4 + 0] += xi * wv.x;
                acc[o4 * 4 + 1] += xi * wv.y;
                acc[o4 * 4 + 2] += xi * wv.z;
                acc[o4 * 4 + 3] += xi * wv.w;
            }
        }
    }

    float4* hout = reinterpret_cast<float4*>(&g_h[(size_t)n * FEAT]);
#pragma unroll
    for (int o4 = 0; o4 < FEAT / 4; o4++)
        hout[o4] = make_float4(acc[o4 * 4 + 0], acc[o4 * 4 + 1],
                               acc[o4 * 4 + 2], acc[o4 * 4 + 3]);

    g_u[n] = u;
    g_v[n] = v;

#pragma unroll
    for (int h = 0; h < NHEAD; h++) {
        float as = 0.f, ad = 0.f;
#pragma unroll
        for (int k = 0; k < HDIM; k++) {
            float hv = acc[h * HDIM + k];
            as += hv * s_wa[k];
            ad += hv * s_wa[HDIM + k];
        }
        g_as[n * NHEAD + h] = as;
        g_ad[n * NHEAD + h] = ad;
    }
}

// ---------------------------------------------------------------------------
// 7) CSR reduce: 16 threads per dst node (t*4 = contiguous float4 of the 64
//    output features; head = t>>2). Register accumulation, no atomics,
//    normalization fused. Every output element written exactly once.
// ---------------------------------------------------------------------------
__global__ void __launch_bounds__(256)
reduce_kernel(float* __restrict__ out, int N) {
    int gid = blockIdx.x * blockDim.x + threadIdx.x;
    int n = gid >> 4;
    if (n >= N) return;
    int t = gid & 15;
    int head = t >> 2;

    int beg = g_offs[n];
    int end = g_offs[n + 1];

    float vofs = g_v[n] + g_P.off;     // folded per-node sign offset
    float adb  = g_ad[n * NHEAD + head] + g_P.ba;

    float4 acc = make_float4(0.f, 0.f, 0.f, 0.f);
    float dsum = 0.f;

#pragma unroll 2
    for (int p = beg; p < end; p++) {
        int s = __ldg(&g_srcs[p]);
        float arg = g_u[s] + vofs;
        float sg = (arg > 0.f) ? 1.f : ((arg < 0.f) ? -1.f : 0.f);
        float al = sg * g_as[s * NHEAD + head] + adb;
        al = (al > 0.f) ? al : 0.01f * al;          // leaky_relu
        float w = __expf(al);
        float4 hv = *reinterpret_cast<const float4*>(&g_h[(size_t)s * FEAT + t * 4]);
        float ws = w * sg;
        acc.x += ws * hv.x;
        acc.y += ws * hv.y;
        acc.z += ws * hv.z;
        acc.w += ws * hv.w;
        dsum += w;
    }

    float inv = 1.f / fmaxf(dsum, 1e-16f);
    *reinterpret_cast<float4*>(&out[(size_t)n * FEAT + t * 4]) =
        make_float4(acc.x * inv, acc.y * inv, acc.z * inv, acc.w * inv);
}

// ---------------------------------------------------------------------------
extern "C" void kernel_launch(void* const* d_in, const int* in_sizes, int n_in,
                              void* d_out, int out_size) {
    const float* x   = (const float*)d_in[0];
    const int*   src = (const int*)  d_in[1];
    const int*   dst = (const int*)  d_in[2];
    const float* Wl  = (const float*)d_in[3];
    const float* bl  = (const float*)d_in[4];
    const float* Wa  = (const float*)d_in[5];
    const float* ba  = (const float*)d_in[6];
    const float* Wd  = (const float*)d_in[7];
    const float* bd  = (const float*)d_in[8];
    const float* Wf  = (const float*)d_in[9];
    const float* bf  = (const float*)d_in[10];
    float* out = (float*)d_out;

    int N = in_sizes[0] / DIN;
    int E = in_sizes[1];
    int NB = (N + SCAN_B - 1) / SCAN_B;

    precompute_kernel<<<1, 64>>>(Wd, bd, Wf, bf, ba);
    zero_deg_kernel<<<(N + 255) / 256, 256>>>(N);
    hist_kernel<<<(E + 255) / 256, 256>>>(dst, E);
    scan_partial_kernel<<<NB, SCAN_B>>>(N);
    scan_base_kernel<<<1, NBMAX>>>(NB, N);
    scan_final_kernel<<<NB, SCAN_B>>>(N);
    scatter_kernel<<<(E + 255) / 256, 256>>>(src, dst, E);
    node_kernel<<<(N + 127) / 128, 128>>>(x, Wl, bl, Wa, N);

    long long threads = (long long)N * 16;
    int blocks = (int)((threads + 255) / 256);
    reduce_kernel<<<blocks, 256>>>(out, N);
}

// round 4
// speedup vs baseline: 1.8370x; 1.1391x over previous
#include <cuda_runtime.h>

#define NMAX   100000
#define EMAX   1600000
#define DIN    64
#define NHEAD  4
#define HDIM   16
#define FEAT   64   // NHEAD*HDIM
#define SCAN_B 1024
#define NBMAX  256

// -------- scratch (static device globals; no allocations allowed) ----------
__device__ __align__(16) static float g_h[(size_t)NMAX * FEAT];   // projected node features
__device__ static float g_u[NMAX];
__device__ static float g_v[NMAX];
__device__ __align__(16) static float g_as[NMAX * NHEAD];
__device__ __align__(16) static float g_ad[NMAX * NHEAD];

__device__ static int g_deg[NMAX];
__device__ static int g_cursor[NMAX];      // initialized to offs; scatter bumps it
__device__ static int g_offs[NMAX + 1];
__device__ static int g_srcs[EMAX];        // src node id per edge, sorted by dst
__device__ static int g_bsum[NBMAX];
__device__ static int g_bbase[NBMAX];

struct Params {
    float cu[DIN];   // Wd @ (Wf[0:64]  + Wf[128:192])
    float cv[DIN];   // Wd @ (Wf[64:128] - Wf[128:192])
    float off;       // bd . (wfu + wfv) + bf
    float ba;        // attention bias scalar
};
__device__ static Params g_P;

// ---------------------------------------------------------------------------
// 1) Fold the rank-1 edge linears into per-node projection vectors.
// ---------------------------------------------------------------------------
__global__ void precompute_kernel(const float* __restrict__ Wd,
                                  const float* __restrict__ bd,
                                  const float* __restrict__ Wf,
                                  const float* __restrict__ bf,
                                  const float* __restrict__ ba) {
    __shared__ float wfu[DIN], wfv[DIN], red[DIN];
    int t = threadIdx.x;   // 64 threads
    float f0 = Wf[t], f1 = Wf[DIN + t], f2 = Wf[2 * DIN + t];
    wfu[t] = f0 + f2;
    wfv[t] = f1 - f2;
    __syncthreads();
    float cu = 0.f, cv = 0.f;
#pragma unroll 8
    for (int j = 0; j < DIN; j++) {
        float w = Wd[t * DIN + j];
        cu += w * wfu[j];
        cv += w * wfv[j];
    }
    g_P.cu[t] = cu;
    g_P.cv[t] = cv;
    red[t] = bd[t] * (wfu[t] + wfv[t]);
    __syncthreads();
    if (t == 0) {
        float s = bf[0];
        for (int j = 0; j < DIN; j++) s += red[j];
        g_P.off = s;
        g_P.ba  = ba[0];
    }
}

// ---------------------------------------------------------------------------
// 2) Zero degree array.
// ---------------------------------------------------------------------------
__global__ void zero_deg_kernel(int N) {
    int i = blockIdx.x * blockDim.x + threadIdx.x;
    if (i < N) g_deg[i] = 0;
}

// ---------------------------------------------------------------------------
// 3) Degree histogram over dst.
// ---------------------------------------------------------------------------
__global__ void hist_kernel(const int* __restrict__ dst, int E) {
    int e = blockIdx.x * blockDim.x + threadIdx.x;
    if (e < E) atomicAdd(&g_deg[dst[e]], 1);
}

// ---------------------------------------------------------------------------
// 4a) Per-block partial sums of g_deg.
// ---------------------------------------------------------------------------
__global__ void scan_partial_kernel(int N) {
    __shared__ int sm[SCAN_B];
    int idx = blockIdx.x * SCAN_B + threadIdx.x;
    sm[threadIdx.x] = (idx < N) ? g_deg[idx] : 0;
    __syncthreads();
#pragma unroll
    for (int o = SCAN_B / 2; o > 0; o >>= 1) {
        if (threadIdx.x < o) sm[threadIdx.x] += sm[threadIdx.x + o];
        __syncthreads();
    }
    if (threadIdx.x == 0) g_bsum[blockIdx.x] = sm[0];
}

// ---------------------------------------------------------------------------
// 4b) Exclusive scan of the (<=256) block sums; also write total at offs[N].
// ---------------------------------------------------------------------------
__global__ void scan_base_kernel(int NB, int N) {
    __shared__ int sm[NBMAX];
    int t = threadIdx.x;   // 256 threads
    int v = (t < NB) ? g_bsum[t] : 0;
    sm[t] = v;
    __syncthreads();
#pragma unroll
    for (int o = 1; o < NBMAX; o <<= 1) {
        int tmp = (t >= o) ? sm[t - o] : 0;
        __syncthreads();
        sm[t] += tmp;
        __syncthreads();
    }
    if (t < NB) g_bbase[t] = sm[t] - v;
    if (t == NBMAX - 1) g_offs[N] = sm[NBMAX - 1];
}

// ---------------------------------------------------------------------------
// 4c) Per-block exclusive scan + base; also seeds the scatter cursor.
// ---------------------------------------------------------------------------
__global__ void scan_final_kernel(int N) {
    __shared__ int sm[SCAN_B];
    int idx = blockIdx.x * SCAN_B + threadIdx.x;
    int v = (idx < N) ? g_deg[idx] : 0;
    sm[threadIdx.x] = v;
    __syncthreads();
#pragma unroll
    for (int o = 1; o < SCAN_B; o <<= 1) {
        int tmp = (threadIdx.x >= o) ? sm[threadIdx.x - o] : 0;
        __syncthreads();
        sm[threadIdx.x] += tmp;
        __syncthreads();
    }
    if (idx < N) {
        int off = g_bbase[blockIdx.x] + sm[threadIdx.x] - v;
        g_offs[idx] = off;
        g_cursor[idx] = off;
    }
}

// ---------------------------------------------------------------------------
// 5) Scatter src ids into dst-sorted order (cursor pre-seeded with offsets).
// ---------------------------------------------------------------------------
__global__ void scatter_kernel(const int* __restrict__ src,
                               const int* __restrict__ dst, int E) {
    int e = blockIdx.x * blockDim.x + threadIdx.x;
    if (e >= E) return;
    int pos = atomicAdd(&g_cursor[dst[e]], 1);
    g_srcs[pos] = src[e];
}

// ---------------------------------------------------------------------------
// 6) Per-node projections: h = x@Wl + bl, u = x.cu, v = x.cv,
//    a_s/a_d = per-head dot with Wa halves.
// ---------------------------------------------------------------------------
__global__ void __launch_bounds__(128)
node_kernel(const float* __restrict__ x,
            const float* __restrict__ Wl,
            const float* __restrict__ bl,
            const float* __restrict__ Wa,
            int N) {
    __shared__ float s_wl[DIN * FEAT];
    __shared__ float s_bl[FEAT];
    __shared__ float s_wa[2 * HDIM];
    __shared__ float s_cu[DIN], s_cv[DIN];

    for (int i = threadIdx.x; i < DIN * FEAT; i += blockDim.x) s_wl[i] = Wl[i];
    if (threadIdx.x < FEAT) {
        s_bl[threadIdx.x] = bl[threadIdx.x];
        s_cu[threadIdx.x] = g_P.cu[threadIdx.x];
        s_cv[threadIdx.x] = g_P.cv[threadIdx.x];
    }
    if (threadIdx.x < 2 * HDIM) s_wa[threadIdx.x] = Wa[threadIdx.x];
    __syncthreads();

    int n = blockIdx.x * blockDim.x + threadIdx.x;
    if (n >= N) return;

    float acc[FEAT];
#pragma unroll
    for (int o = 0; o < FEAT; o++) acc[o] = s_bl[o];
    float u = 0.f, v = 0.f;

    const float4* xr = reinterpret_cast<const float4*>(x + (size_t)n * DIN);
#pragma unroll 1
    for (int i4 = 0; i4 < DIN / 4; i4++) {
        float4 xv = xr[i4];
        float xs[4] = {xv.x, xv.y, xv.z, xv.w};
#pragma unroll
        for (int j = 0; j < 4; j++) {
            int i = i4 * 4 + j;
            float xi = xs[j];
            u += xi * s_cu[i];
            v += xi * s_cv[i];
            const float4* wrow = reinterpret_cast<const float4*>(&s_wl[i * FEAT]);
#pragma unroll
            for (int o4 = 0; o4 < FEAT / 4; o4++) {
                float4 wv = wrow[o4];
                acc[o4 * 4 + 0] += xi * wv.x;
                acc[o4 * 4 + 1] += xi * wv.y;
                acc[o4 * 4 + 2] += xi * wv.z;
                acc[o4 * 4 + 3] += xi * wv.w;
            }
        }
    }

    float4* hout = reinterpret_cast<float4*>(&g_h[(size_t)n * FEAT]);
#pragma unroll
    for (int o4 = 0; o4 < FEAT / 4; o4++)
        hout[o4] = make_float4(acc[o4 * 4 + 0], acc[o4 * 4 + 1],
                               acc[o4 * 4 + 2], acc[o4 * 4 + 3]);

    g_u[n] = u;
    g_v[n] = v;

#pragma unroll
    for (int h = 0; h < NHEAD; h++) {
        float as = 0.f, ad = 0.f;
#pragma unroll
        for (int k = 0; k < HDIM; k++) {
            float hv = acc[h * HDIM + k];
            as += hv * s_wa[k];
            ad += hv * s_wa[HDIM + k];
        }
        g_as[n * NHEAD + h] = as;
        g_ad[n * NHEAD + h] = ad;
    }
}

// ---------------------------------------------------------------------------
// 7) CSR reduce: 16 threads per dst node (t*4 = contiguous float4 of the 64
//    output features; head = t>>2). Register accumulation, no atomics,
//    normalization fused; src-index load software-pipelined one iter ahead.
// ---------------------------------------------------------------------------
__global__ void __launch_bounds__(256)
reduce_kernel(float* __restrict__ out, int N) {
    int gid = blockIdx.x * blockDim.x + threadIdx.x;
    int n = gid >> 4;
    if (n >= N) return;
    int t = gid & 15;
    int head = t >> 2;

    int beg = g_offs[n];
    int end = g_offs[n + 1];

    float vofs = g_v[n] + g_P.off;     // folded per-node sign offset
    float adb  = g_ad[n * NHEAD + head] + g_P.ba;

    float4 acc = make_float4(0.f, 0.f, 0.f, 0.f);
    float dsum = 0.f;

    if (beg < end) {
        int s = __ldg(&g_srcs[beg]);
        for (int p = beg; p < end; p++) {
            int s_next = (p + 1 < end) ? __ldg(&g_srcs[p + 1]) : 0;
            float u  = __ldg(&g_u[s]);
            float as = __ldg(&g_as[s * NHEAD + head]);
            float4 hv = *reinterpret_cast<const float4*>(&g_h[(size_t)s * FEAT + t * 4]);

            float arg = u + vofs;
            float sg = (arg > 0.f) ? 1.f : ((arg < 0.f) ? -1.f : 0.f);
            float al = sg * as + adb;
            al = (al > 0.f) ? al : 0.01f * al;          // leaky_relu
            float w = __expf(al);
            float ws = w * sg;
            acc.x += ws * hv.x;
            acc.y += ws * hv.y;
            acc.z += ws * hv.z;
            acc.w += ws * hv.w;
            dsum += w;
            s = s_next;
        }
    }

    float inv = 1.f / fmaxf(dsum, 1e-16f);
    *reinterpret_cast<float4*>(&out[(size_t)n * FEAT + t * 4]) =
        make_float4(acc.x * inv, acc.y * inv, acc.z * inv, acc.w * inv);
}

// ---------------------------------------------------------------------------
extern "C" void kernel_launch(void* const* d_in, const int* in_sizes, int n_in,
                              void* d_out, int out_size) {
    const float* x   = (const float*)d_in[0];
    const int*   src = (const int*)  d_in[1];
    const int*   dst = (const int*)  d_in[2];
    const float* Wl  = (const float*)d_in[3];
    const float* bl  = (const float*)d_in[4];
    const float* Wa  = (const float*)d_in[5];
    const float* ba  = (const float*)d_in[6];
    const float* Wd  = (const float*)d_in[7];
    const float* bd  = (const float*)d_in[8];
    const float* Wf  = (const float*)d_in[9];
    const float* bf  = (const float*)d_in[10];
    float* out = (float*)d_out;

    int N = in_sizes[0] / DIN;
    int E = in_sizes[1];
    int NB = (N + SCAN_B - 1) / SCAN_B;

    // One-time stream/event setup (host resources, not device memory).
    static cudaStream_t s_side = nullptr;
    static cudaEvent_t  ev_fork = nullptr, ev_join = nullptr;
    if (s_side == nullptr) {
        cudaStreamCreateWithFlags(&s_side, cudaStreamNonBlocking);
        cudaEventCreateWithFlags(&ev_fork, cudaEventDisableTiming);
        cudaEventCreateWithFlags(&ev_join, cudaEventDisableTiming);
    }

    // Fork: side stream builds the CSR (memory/atomic-bound) while the main
    // stream runs the dense projections (FFMA-bound).
    cudaEventRecord(ev_fork, 0);
    cudaStreamWaitEvent(s_side, ev_fork, 0);

    zero_deg_kernel<<<(N + 255) / 256, 256, 0, s_side>>>(N);
    hist_kernel<<<(E + 255) / 256, 256, 0, s_side>>>(dst, E);
    scan_partial_kernel<<<NB, SCAN_B, 0, s_side>>>(N);
    scan_base_kernel<<<1, NBMAX, 0, s_side>>>(NB, N);
    scan_final_kernel<<<NB, SCAN_B, 0, s_side>>>(N);
    scatter_kernel<<<(E + 255) / 256, 256, 0, s_side>>>(src, dst, E);
    cudaEventRecord(ev_join, s_side);

    precompute_kernel<<<1, 64>>>(Wd, bd, Wf, bf, ba);
    node_kernel<<<(N + 127) / 128, 128>>>(x, Wl, bl, Wa, N);

    // Join, then reduce.
    cudaStreamWaitEvent(0, ev_join, 0);
    long long threads = (long long)N * 16;
    int blocks = (int)((threads + 255) / 256);
    reduce_kernel<<<blocks, 256>>>(out, N);
}